// round 17
// baseline (speedup 1.0000x reference)
#include <cuda_runtime.h>
#include <cuda_fp16.h>
#include <cstdint>
#include <cstddef>

#define N_NODES 102400
#define N_EDGES 1638400
#define N_REL   8
#define D0      256
#define D1      128
#define D2      64

// ---------------- scratch (device globals; no allocation allowed) ----------
__device__ __align__(16) __half   g_a1h[(size_t)N_NODES * D0];             // 52 MB fp16 b_z
__device__ __align__(16) uint32_t g_xw1[(size_t)N_REL * N_NODES * D1 / 2]; // 210 MB fp16
__device__ __align__(16) uint32_t g_h1 [(size_t)N_NODES * D1 / 2];         // 26 MB fp16
__device__ __align__(16) uint32_t g_xw2[(size_t)N_REL * N_NODES * D2 / 2]; // 105 MB fp16
__device__ __align__(16) uint32_t g_h2 [(size_t)N_NODES * D2 / 2];         // 13 MB fp16
__device__ __align__(16) float    g_xw3[(size_t)N_REL * N_NODES];          // 3.3 MB
__device__ __align__(16) __half   g_w1t[(size_t)N_REL * D1 * D0];          // 0.5 MB [r][n][k]
__device__ __align__(16) __half   g_w2t[(size_t)N_REL * D2 * D1];          // 0.13 MB

// CSR-by-dst edge structure (packed: .x = src | t<<20, .y = weight bits)
__device__ int   g_deg[N_NODES];
__device__ int   g_fil[N_NODES];
__device__ int   g_off[N_NODES + 1];
__device__ int   g_bsum[400];
__device__ __align__(16) uint2 g_epk[N_EDGES];   // 12.6 MB

__device__ __forceinline__ uint32_t pack_f16x2(float lo, float hi) {
    uint32_t r;
    asm("cvt.rn.f16x2.f32 %0, %1, %2;" : "=r"(r) : "f"(hi), "f"(lo));
    return r;
}

__device__ __forceinline__ float2 unpack_f16x2(uint32_t u) {
    __half2 h = *reinterpret_cast<__half2*>(&u);
    return __half22float2(h);
}

__device__ __forceinline__ void mma_f16(float* c, const uint32_t* a,
                                        uint32_t b0, uint32_t b1) {
    asm volatile(
        "mma.sync.aligned.m16n8k16.row.col.f32.f16.f16.f32 "
        "{%0,%1,%2,%3}, {%4,%5,%6,%7}, {%8,%9}, {%0,%1,%2,%3};"
        : "+f"(c[0]), "+f"(c[1]), "+f"(c[2]), "+f"(c[3])
        : "r"(a[0]), "r"(a[1]), "r"(a[2]), "r"(a[3]), "r"(b0), "r"(b1));
}

__device__ __forceinline__ void ldsm_x4(uint32_t* r, uint32_t saddr) {
    asm volatile(
        "ldmatrix.sync.aligned.m8n8.x4.shared.b16 {%0,%1,%2,%3}, [%4];"
        : "=r"(r[0]), "=r"(r[1]), "=r"(r[2]), "=r"(r[3]) : "r"(saddr));
}

__device__ __forceinline__ uint32_t smem_u32(const void* p) {
    return (uint32_t)__cvta_generic_to_shared(p);
}

#define CP_ASYNC16(dst, src) \
    asm volatile("cp.async.cg.shared.global [%0], [%1], 16;" \
                 :: "r"(dst), "l"(src) : "memory")
#define CP_COMMIT() asm volatile("cp.async.commit_group;" ::: "memory")
#define CP_WAIT(n)  asm volatile("cp.async.wait_group %0;" :: "n"(n) : "memory")

// ============== cp.async 3-buffer fp16 batched GEMM (fp32 accum) ===========
// C[r] slab = A @ Bt[r, n0:n0+BN]^T.  BN=64: acc=32 regs -> 3 CTAs/SM.
// blockIdx = (relation, m-tile, n-half). 8 warps 4(M) x 2(N). PAD2=40.
template<int BN, int Kdim, int NTOT>
__global__ __launch_bounds__(256, 3)
void rgemm_h(const __half* __restrict__ A, const __half* __restrict__ Bt,
             uint32_t* __restrict__ C) {
    constexpr int BM = 128, BK = 32, PAD2 = 40;
    constexpr int NCH = Kdim / BK;
    constexpr int WN = BN / 2, NT = WN / 8, NP = NT / 2;
    constexpr int ASTR = BM * PAD2;
    constexpr int BSTR = BN * PAD2;

    extern __shared__ __align__(16) __half smh[];
    __half* Asm = smh;                       // [3][BM][PAD2]
    __half* Bsm = smh + 3 * ASTR;            // [3][BN][PAD2]

    const int r   = blockIdx.x;
    const int m0  = blockIdx.y * BM;
    const int n0  = blockIdx.z * BN;
    const int tid = threadIdx.x;
    const int lane = tid & 31, wid = tid >> 5;
    const int mi = wid & 3, ni = wid >> 2;
    const int g = lane >> 2, t = lane & 3;

    const __half* Ab = A + (size_t)m0 * Kdim;
    const __half* Bb = Bt + ((size_t)r * NTOT + n0) * Kdim;
    uint32_t*     Cr = C + (size_t)r * N_NODES * (NTOT / 2)
                         + (size_t)m0 * (NTOT / 2) + n0 / 2;

    const int j8 = lane >> 3, i8 = lane & 7;
    uint32_t aAddr[2];
#pragma unroll
    for (int mt = 0; mt < 2; mt++) {
        int row = mi * 32 + mt * 16 + (j8 & 1) * 8 + i8;
        aAddr[mt] = smem_u32(&Asm[row * PAD2]) + (j8 >> 1) * 16;
    }
    uint32_t bAddr[NP];
#pragma unroll
    for (int p = 0; p < NP; p++) {
        int nrow = ni * WN + p * 16 + (j8 >> 1) * 8 + i8;
        bAddr[p] = smem_u32(&Bsm[nrow * PAD2]) + (j8 & 1) * 16;
    }

    auto load_stage = [&](int c, int s) {
        __half* Ad = Asm + s * ASTR;
#pragma unroll
        for (int i = 0; i < 2; i++) {
            int idx = i * 256 + tid;
            int row = idx >> 2, ch = (idx & 3) * 8;
            CP_ASYNC16(smem_u32(Ad + row * PAD2 + ch),
                       Ab + (size_t)row * Kdim + c * BK + ch);
        }
        __half* Bd = Bsm + s * BSTR;
        {
            int row = tid >> 2, ch = (tid & 3) * 8;
            CP_ASYNC16(smem_u32(Bd + row * PAD2 + ch),
                       Bb + (size_t)row * Kdim + c * BK + ch);
        }
        CP_COMMIT();
    };

    float acc[2][NT][4];
#pragma unroll
    for (int mt = 0; mt < 2; mt++)
#pragma unroll
        for (int nt = 0; nt < NT; nt++)
#pragma unroll
            for (int q = 0; q < 4; q++) acc[mt][nt][q] = 0.f;

    load_stage(0, 0);
    load_stage(1, 1);

    for (int c = 0; c < NCH; c++) {
        const int s = c % 3;
        CP_WAIT(1);
        __syncthreads();
        if (c + 2 < NCH) load_stage(c + 2, (c + 2) % 3);
        else CP_COMMIT();

        const uint32_t ao = (uint32_t)s * ASTR * 2, bo = (uint32_t)s * BSTR * 2;
#pragma unroll
        for (int kk = 0; kk < 2; kk++) {
            uint32_t a[2][4];
            ldsm_x4(a[0], aAddr[0] + ao + kk * 32);
            ldsm_x4(a[1], aAddr[1] + ao + kk * 32);
#pragma unroll
            for (int p = 0; p < NP; p++) {
                uint32_t b[4];
                ldsm_x4(b, bAddr[p] + bo + kk * 32);
#pragma unroll
                for (int mt = 0; mt < 2; mt++) {
                    mma_f16(acc[mt][2 * p],     a[mt], b[0], b[1]);
                    mma_f16(acc[mt][2 * p + 1], a[mt], b[2], b[3]);
                }
            }
        }
    }

#pragma unroll
    for (int mt = 0; mt < 2; mt++) {
        int row = mi * 32 + mt * 16 + g;
#pragma unroll
        for (int nt = 0; nt < NT; nt++) {
            int col2 = (ni * WN + nt * 8) / 2 + t;
            Cr[(size_t)row * (NTOT / 2) + col2] =
                pack_f16x2(acc[mt][nt][0], acc[mt][nt][1]);
            Cr[(size_t)(row + 8) * (NTOT / 2) + col2] =
                pack_f16x2(acc[mt][nt][2], acc[mt][nt][3]);
        }
    }
}

// ---- fused prep: b_z fp32->fp16, W1/W2 transpose+convert (one launch) -----
// grid.x = 12800 (A) + 1024 (W1) + 256 (W2) blocks of 256 threads.
#define PREP_A_BLOCKS  12800
#define PREP_W1_BLOCKS 1024
__global__ void prep_all(const float* __restrict__ b_z,
                         const float* __restrict__ W1,
                         const float* __restrict__ W2,
                         uint32_t* __restrict__ a1h,
                         __half* __restrict__ w1t,
                         __half* __restrict__ w2t) {
    int bx = blockIdx.x;
    if (bx < PREP_A_BLOCKS) {
        size_t i = (size_t)bx * 256 + threadIdx.x;   // i indexes groups of 8
        float4 v0 = *(const float4*)(b_z + i * 8);
        float4 v1 = *(const float4*)(b_z + i * 8 + 4);
        uint4 o;
        o.x = pack_f16x2(v0.x, v0.y);
        o.y = pack_f16x2(v0.z, v0.w);
        o.z = pack_f16x2(v1.x, v1.y);
        o.w = pack_f16x2(v1.z, v1.w);
        *(uint4*)(a1h + i * 4) = o;
    } else if (bx < PREP_A_BLOCKS + PREP_W1_BLOCKS) {
        int idx = (bx - PREP_A_BLOCKS) * 256 + threadIdx.x;  // r*K*N layout
        int r = idx / (D0 * D1), rem = idx % (D0 * D1);
        int k = rem / D1, n = rem % D1;
        w1t[((size_t)r * D1 + n) * D0 + k] =
            __float2half_rn(W1[((size_t)r * D0 + k) * D1 + n]);
    } else {
        int idx = (bx - PREP_A_BLOCKS - PREP_W1_BLOCKS) * 256 + threadIdx.x;
        int r = idx / (D1 * D2), rem = idx % (D1 * D2);
        int k = rem / D2, n = rem % D2;
        w2t[((size_t)r * D2 + n) * D1 + k] =
            __float2half_rn(W2[((size_t)r * D1 + k) * D2 + n]);
    }
}

// ================= CSR build (by dst) =======================================
__global__ void csr_zero() {
    int i = blockIdx.x * 256 + threadIdx.x;
    if (i < N_NODES) { g_deg[i] = 0; g_fil[i] = 0; }
}

__global__ void csr_count(const int* __restrict__ eidx) {
    int e = blockIdx.x * 256 + threadIdx.x;
    if (e < N_EDGES) atomicAdd(&g_deg[eidx[N_EDGES + e]], 1);
}

__global__ void scan_blocks() {
    __shared__ int s[256];
    int i = blockIdx.x * 256 + threadIdx.x;
    int v = g_deg[i];
    s[threadIdx.x] = v; __syncthreads();
    for (int d = 1; d < 256; d <<= 1) {
        int x = (threadIdx.x >= d) ? s[threadIdx.x - d] : 0;
        __syncthreads();
        s[threadIdx.x] += x;
        __syncthreads();
    }
    g_off[i] = s[threadIdx.x] - v;
    if (threadIdx.x == 255) g_bsum[blockIdx.x] = s[255];
}

__global__ void scan_tops() {
    __shared__ int s[512];
    int t = threadIdx.x;
    int v = (t < 400) ? g_bsum[t] : 0;
    s[t] = v; __syncthreads();
    for (int d = 1; d < 512; d <<= 1) {
        int x = (t >= d) ? s[t - d] : 0;
        __syncthreads();
        s[t] += x;
        __syncthreads();
    }
    if (t < 400) g_bsum[t] = s[t] - v;
    if (t == 0) g_off[N_NODES] = N_EDGES;
}

__global__ void scan_add() {
    int i = blockIdx.x * 256 + threadIdx.x;
    g_off[i] += g_bsum[blockIdx.x];
}

__global__ void csr_fill(const int* __restrict__ eidx,
                         const float* __restrict__ ew,
                         const int* __restrict__ et) {
    int e = blockIdx.x * 256 + threadIdx.x;
    if (e >= N_EDGES) return;
    int src = eidx[e], dst = eidx[N_EDGES + e], t = et[e];
    int pos = g_off[dst] + atomicAdd(&g_fil[dst], 1);
    g_epk[pos] = make_uint2((uint32_t)src | ((uint32_t)t << 20),
                            __float_as_uint(ew[e]));
}

// ===== CSR gather-aggregate (fp16 xw -> fp16 h), 4x unrolled ===============
template<int D>
__global__ void agg_csr(const uint32_t* __restrict__ xw,
                        const float* __restrict__ bias,
                        uint32_t* __restrict__ hout) {
    constexpr int L = D / 8;
    int gt = blockIdx.x * blockDim.x + threadIdx.x;
    int node = gt / L;
    int sub  = gt % L;
    if (node >= N_NODES) return;
    int beg = g_off[node], end = g_off[node + 1];

    float acc[8];
#pragma unroll
    for (int q = 0; q < 8; q++) acc[q] = 0.f;

    const uint4* xw4 = (const uint4*)xw;
    int j = beg;
    for (; j + 4 <= end; j += 4) {
        uint2 e0 = g_epk[j],     e1 = g_epk[j + 1];
        uint2 e2 = g_epk[j + 2], e3 = g_epk[j + 3];
        uint4 v0 = xw4[((size_t)(e0.x >> 20) * N_NODES + (e0.x & 0xFFFFF)) * (D / 8) + sub];
        uint4 v1 = xw4[((size_t)(e1.x >> 20) * N_NODES + (e1.x & 0xFFFFF)) * (D / 8) + sub];
        uint4 v2 = xw4[((size_t)(e2.x >> 20) * N_NODES + (e2.x & 0xFFFFF)) * (D / 8) + sub];
        uint4 v3 = xw4[((size_t)(e3.x >> 20) * N_NODES + (e3.x & 0xFFFFF)) * (D / 8) + sub];
        float w0 = __uint_as_float(e0.y), w1 = __uint_as_float(e1.y);
        float w2 = __uint_as_float(e2.y), w3 = __uint_as_float(e3.y);
        float2 f;
        f = unpack_f16x2(v0.x); acc[0] += f.x * w0; acc[1] += f.y * w0;
        f = unpack_f16x2(v0.y); acc[2] += f.x * w0; acc[3] += f.y * w0;
        f = unpack_f16x2(v0.z); acc[4] += f.x * w0; acc[5] += f.y * w0;
        f = unpack_f16x2(v0.w); acc[6] += f.x * w0; acc[7] += f.y * w0;
        f = unpack_f16x2(v1.x); acc[0] += f.x * w1; acc[1] += f.y * w1;
        f = unpack_f16x2(v1.y); acc[2] += f.x * w1; acc[3] += f.y * w1;
        f = unpack_f16x2(v1.z); acc[4] += f.x * w1; acc[5] += f.y * w1;
        f = unpack_f16x2(v1.w); acc[6] += f.x * w1; acc[7] += f.y * w1;
        f = unpack_f16x2(v2.x); acc[0] += f.x * w2; acc[1] += f.y * w2;
        f = unpack_f16x2(v2.y); acc[2] += f.x * w2; acc[3] += f.y * w2;
        f = unpack_f16x2(v2.z); acc[4] += f.x * w2; acc[5] += f.y * w2;
        f = unpack_f16x2(v2.w); acc[6] += f.x * w2; acc[7] += f.y * w2;
        f = unpack_f16x2(v3.x); acc[0] += f.x * w3; acc[1] += f.y * w3;
        f = unpack_f16x2(v3.y); acc[2] += f.x * w3; acc[3] += f.y * w3;
        f = unpack_f16x2(v3.z); acc[4] += f.x * w3; acc[5] += f.y * w3;
        f = unpack_f16x2(v3.w); acc[6] += f.x * w3; acc[7] += f.y * w3;
    }
    for (; j < end; j++) {
        uint2 e0 = g_epk[j];
        uint4 v0 = xw4[((size_t)(e0.x >> 20) * N_NODES + (e0.x & 0xFFFFF)) * (D / 8) + sub];
        float w0 = __uint_as_float(e0.y);
        float2 f;
        f = unpack_f16x2(v0.x); acc[0] += f.x * w0; acc[1] += f.y * w0;
        f = unpack_f16x2(v0.y); acc[2] += f.x * w0; acc[3] += f.y * w0;
        f = unpack_f16x2(v0.z); acc[4] += f.x * w0; acc[5] += f.y * w0;
        f = unpack_f16x2(v0.w); acc[6] += f.x * w0; acc[7] += f.y * w0;
    }
    float4 b0 = *(const float4*)&bias[sub * 8];
    float4 b1 = *(const float4*)&bias[sub * 8 + 4];
    uint4 o;
    o.x = pack_f16x2(fmaxf(acc[0] + b0.x, 0.f), fmaxf(acc[1] + b0.y, 0.f));
    o.y = pack_f16x2(fmaxf(acc[2] + b0.z, 0.f), fmaxf(acc[3] + b0.w, 0.f));
    o.z = pack_f16x2(fmaxf(acc[4] + b1.x, 0.f), fmaxf(acc[5] + b1.y, 0.f));
    o.w = pack_f16x2(fmaxf(acc[6] + b1.z, 0.f), fmaxf(acc[7] + b1.w, 0.f));
    *(uint4*)&hout[(size_t)node * (D / 2) + sub * 4] = o;
}

// layer 3: lane-per-edge + warp reduce (no relu on output)
__global__ void agg_out(const float* __restrict__ xw3,
                        const float* __restrict__ b3,
                        float* __restrict__ out) {
    int node = (blockIdx.x * blockDim.x + threadIdx.x) >> 5;
    int lane = threadIdx.x & 31;
    if (node >= N_NODES) return;
    int beg = g_off[node], end = g_off[node + 1];
    float s = 0.f;
    for (int j = beg + lane; j < end; j += 32) {
        uint2 e = g_epk[j];
        s += xw3[(size_t)(e.x >> 20) * N_NODES + (e.x & 0xFFFFF)]
             * __uint_as_float(e.y);
    }
#pragma unroll
    for (int o = 16; o; o >>= 1) s += __shfl_down_sync(0xffffffff, s, o);
    if (lane == 0) out[node] = s + b3[0];
}

// ---------------- layer-3 transform: xw3[r,n] = h2[n] . W3[r] (h2 fp16) ----
__global__ void gemm3_kernel(const uint32_t* __restrict__ h2,
                             const float* __restrict__ W3,
                             float* __restrict__ xw3) {
    __shared__ float w[N_REL][D2];
    for (int i = threadIdx.x; i < N_REL * D2; i += blockDim.x)
        w[i / D2][i % D2] = W3[i];
    __syncthreads();

    int n = blockIdx.x * blockDim.x + threadIdx.x;
    if (n >= N_NODES) return;

    float acc[N_REL];
#pragma unroll
    for (int r = 0; r < N_REL; r++) acc[r] = 0.f;

    const uint32_t* hp = &h2[(size_t)n * (D2 / 2)];
#pragma unroll
    for (int k2 = 0; k2 < D2 / 2; k2++) {
        float2 f = unpack_f16x2(hp[k2]);
#pragma unroll
        for (int r = 0; r < N_REL; r++) {
            acc[r] += f.x * w[r][k2 * 2 + 0];
            acc[r] += f.y * w[r][k2 * 2 + 1];
        }
    }
#pragma unroll
    for (int r = 0; r < N_REL; r++)
        xw3[(size_t)r * N_NODES + n] = acc[r];
}

// ---------------- launcher --------------------------------------------------
extern "C" void kernel_launch(void* const* d_in, const int* in_sizes, int n_in,
                              void* d_out, int out_size) {
    const float* b_z  = (const float*)d_in[0];
    const int*   eidx = (const int*)d_in[1];
    const float* ew   = (const float*)d_in[2];
    const int*   et   = (const int*)d_in[3];
    const float* W1   = (const float*)d_in[4];
    const float* b1   = (const float*)d_in[5];
    const float* W2   = (const float*)d_in[6];
    const float* b2   = (const float*)d_in[7];
    const float* W3   = (const float*)d_in[8];
    const float* b3   = (const float*)d_in[9];
    float*       out  = (float*)d_out;

    void* p;
    __half *a1h, *w1t, *w2t;
    uint32_t *xw1, *xw2, *h1, *h2;
    float *xw3;
    cudaGetSymbolAddress(&p, g_a1h); a1h = (__half*)p;
    cudaGetSymbolAddress(&p, g_xw1); xw1 = (uint32_t*)p;
    cudaGetSymbolAddress(&p, g_h1 ); h1  = (uint32_t*)p;
    cudaGetSymbolAddress(&p, g_xw2); xw2 = (uint32_t*)p;
    cudaGetSymbolAddress(&p, g_h2 ); h2  = (uint32_t*)p;
    cudaGetSymbolAddress(&p, g_xw3); xw3 = (float*)p;
    cudaGetSymbolAddress(&p, g_w1t); w1t = (__half*)p;
    cudaGetSymbolAddress(&p, g_w2t); w2t = (__half*)p;

    const int smemg = 3 * (128 + 64) * 40 * 2;   // 46080
    cudaFuncSetAttribute(rgemm_h<64, 256, 128>,
                         cudaFuncAttributeMaxDynamicSharedMemorySize, smemg);
    cudaFuncSetAttribute(rgemm_h<64, 128, 64>,
                         cudaFuncAttributeMaxDynamicSharedMemorySize, smemg);

    // launch order arranged so GEMM1 is the 6th launch (ncu -s 5 -c 1).
    csr_zero<<<400, 256>>>();                                       // 1
    prep_all<<<PREP_A_BLOCKS + PREP_W1_BLOCKS + 256, 256>>>(        // 2
        b_z, W1, W2, (uint32_t*)a1h, w1t, w2t);
    csr_count<<<N_EDGES / 256, 256>>>(eidx);                        // 3
    scan_blocks<<<400, 256>>>();                                    // 4
    scan_tops<<<1, 512>>>();                                        // 5
    rgemm_h<64, 256, 128>                                           // 6 (profiled)
        <<<dim3(N_REL, N_NODES / 128, 2), 256, smemg>>>(a1h, w1t, xw1);
    scan_add<<<400, 256>>>();                                       // 7
    csr_fill<<<N_EDGES / 256, 256>>>(eidx, ew, et);                 // 8
    agg_csr<D1><<<N_NODES * (D1 / 8) / 256, 256>>>(xw1, b1, h1);    // 9
    rgemm_h<64, 128, 64>                                            // 10
        <<<dim3(N_REL, N_NODES / 128, 1), 256, smemg>>>((const __half*)h1, w2t, xw2);
    agg_csr<D2><<<N_NODES * (D2 / 8) / 256, 256>>>(xw2, b2, h2);    // 11
    gemm3_kernel<<<(N_NODES + 255) / 256, 256>>>(h2, W3, xw3);      // 12
    agg_out<<<N_NODES * 32 / 256, 256>>>(xw3, b3, out);             // 13
}